// round 16
// baseline (speedup 1.0000x reference)
#include <cuda_runtime.h>
#include <math.h>
#include <stdint.h>

// ---------------- problem constants (fixed by the dataset) ----------------
#define N_M   8192
#define N_D   6144
#define NTOT  14336            // N_M + N_D
#define E_MM  131072
#define E_DD  98304
#define E_G   229376
#define EG_TOT (E_G + NTOT)    // real edges + self loops = 243712
#define HID   128
#define TPB   256

// ---------------- scratch (static device globals; no runtime alloc) -------
__device__ float g_ew_m[E_MM];
__device__ float g_ew_d[E_DD];
__device__ float g_deg_m[N_M];
__device__ float g_deg_d[N_D];
__device__ int   g_cnt_m[N_M],  g_row_m[N_M + 1],  g_cur_m[N_M];
__device__ int   g_src_m[E_MM];  __device__ float g_w_m[E_MM];
__device__ int   g_cnt_d[N_D],  g_row_d[N_D + 1],  g_cur_d[N_D];
__device__ int   g_src_d[E_DD];  __device__ float g_w_d[E_DD];
__device__ int   g_cnt_g[NTOT], g_row_g[NTOT + 1], g_cur_g[NTOT];
__device__ int   g_src_g[EG_TOT];
__device__ float g_bufA[(size_t)NTOT * 256];
__device__ float g_bufB[(size_t)NTOT * 256];
__device__ float g_tmp [(size_t)NTOT * 128];
__device__ float g_xjk [(size_t)NTOT * 224];

__device__ __forceinline__ float4 ld4(const float* p) { return *(const float4*)p; }

// tf32 split via mantissa mask (full-rate LOP3 instead of quarter-rate CVT).
__device__ __forceinline__ uint32_t tfmask(float x) {
    return __float_as_uint(x) & 0xFFFFE000u;
}

// one m16n8k8 tf32 mma, D += A*B (D==C in-place)
__device__ __forceinline__ void mma8(float* d, const uint32_t* a, uint32_t b0, uint32_t b1) {
    asm("mma.sync.aligned.m16n8k8.row.col.f32.tf32.tf32.f32 "
        "{%0,%1,%2,%3}, {%4,%5,%6,%7}, {%8,%9}, {%0,%1,%2,%3};"
        : "+f"(d[0]), "+f"(d[1]), "+f"(d[2]), "+f"(d[3])
        : "r"(a[0]), "r"(a[1]), "r"(a[2]), "r"(a[3]), "r"(b0), "r"(b1));
}

// ldmatrix x4 (b16 form; four 8x4-of-b32 tiles for tf32 fragments)
__device__ __forceinline__ void ldsm4(uint32_t& r0, uint32_t& r1, uint32_t& r2,
                                      uint32_t& r3, uint32_t addr) {
    asm volatile("ldmatrix.sync.aligned.m8n8.x4.shared.b16 {%0,%1,%2,%3}, [%4];"
        : "=r"(r0), "=r"(r1), "=r"(r2), "=r"(r3) : "r"(addr));
}

// cp.async 16B global->shared
__device__ __forceinline__ void cpa16(uint32_t dst, const float* src) {
    asm volatile("cp.async.cg.shared.global [%0], [%1], 16;" :: "r"(dst), "l"(src));
}
__device__ __forceinline__ void cpa_commit() {
    asm volatile("cp.async.commit_group;");
}

// ---------------- init ----------------
__global__ void k_init() {
    int i = blockIdx.x * blockDim.x + threadIdx.x;
    if (i < N_M)  { g_deg_m[i] = 1.0f; g_cnt_m[i] = 0; }   // self-loop weight 1
    if (i < N_D)  { g_deg_d[i] = 1.0f; g_cnt_d[i] = 0; }
    if (i < NTOT) { g_cnt_g[i] = 1; }                       // self loop pre-counted
}

// ---------------- combined edge prep (both GCN graphs + GAT count) --------
__global__ void k_prep_all(const int* __restrict__ e_mm, const float* __restrict__ msM,
                           const int* __restrict__ e_dd, const float* __restrict__ dsM,
                           const int* __restrict__ e_g) {
    int i = blockIdx.x * blockDim.x + threadIdx.x;
    if (i < E_MM) {
        int s = e_mm[i], d = e_mm[E_MM + i];
        float w = msM[(size_t)s * N_M + d];
        g_ew_m[i] = w;
        atomicAdd(&g_deg_m[d], w);
        atomicAdd(&g_cnt_m[d], 1);
    } else if (i < E_MM + E_DD) {
        int f = i - E_MM;
        int s = e_dd[f], d = e_dd[E_DD + f];
        float w = dsM[(size_t)s * N_D + d];
        g_ew_d[f] = w;
        atomicAdd(&g_deg_d[d], w);
        atomicAdd(&g_cnt_d[d], 1);
    } else if (i < E_MM + E_DD + E_G) {
        int f = i - E_MM - E_DD;
        atomicAdd(&g_cnt_g[e_g[E_G + f]], 1);
    }
}

// ---------------- 3 scans in one launch (blockIdx picks the graph) --------
__global__ void k_scan3() {
    __shared__ int sh[1024];
    const int* cnt; int* row; int* cur; int n;
    if (blockIdx.x == 0)      { cnt = g_cnt_m; row = g_row_m; cur = g_cur_m; n = N_M; }
    else if (blockIdx.x == 1) { cnt = g_cnt_d; row = g_row_d; cur = g_cur_d; n = N_D; }
    else                      { cnt = g_cnt_g; row = g_row_g; cur = g_cur_g; n = NTOT; }
    int t = threadIdx.x;
    int chunk = (n + 1023) / 1024;
    int lo = t * chunk, hi = min(lo + chunk, n);
    int sum = 0;
    for (int i = lo; i < hi; i++) sum += cnt[i];
    sh[t] = sum;
    __syncthreads();
    for (int off = 1; off < 1024; off <<= 1) {
        int v = 0;
        if (t >= off) v = sh[t - off];
        __syncthreads();
        if (t >= off) sh[t] += v;
        __syncthreads();
    }
    int run = (t == 0) ? 0 : sh[t - 1];
    for (int i = lo; i < hi; i++) { row[i] = run; cur[i] = run; run += cnt[i]; }
    if (t == 1023) row[n] = sh[1023];
}

// ---------------- combined CSR fill; GCN norm computed inline -------------
__global__ void k_fill_all(const int* __restrict__ e_mm, const int* __restrict__ e_dd,
                           const int* __restrict__ e_g) {
    int i = blockIdx.x * blockDim.x + threadIdx.x;
    if (i < E_MM) {
        int s = e_mm[i], d = e_mm[E_MM + i];
        int p = atomicAdd(&g_cur_m[d], 1);
        g_src_m[p] = s;
        g_w_m[p] = rsqrtf(g_deg_m[s]) * g_ew_m[i] * rsqrtf(g_deg_m[d]);
    } else if (i < E_MM + E_DD) {
        int f = i - E_MM;
        int s = e_dd[f], d = e_dd[E_DD + f];
        int p = atomicAdd(&g_cur_d[d], 1);
        g_src_d[p] = s;
        g_w_d[p] = rsqrtf(g_deg_d[s]) * g_ew_d[f] * rsqrtf(g_deg_d[d]);
    } else if (i < E_MM + E_DD + E_G) {
        int f = i - E_MM - E_DD;
        int d = e_g[E_G + f];
        int p = atomicAdd(&g_cur_g[d], 1);
        g_src_g[p] = e_g[f];
    } else if (i < E_MM + E_DD + E_G + NTOT) {
        int f = i - E_MM - E_DD - E_G;     // self loop
        int p = atomicAdd(&g_cur_g[f], 1);
        g_src_g[p] = f;
    }
}

// ---------------- tf32x3 tensor-core GEMM: BMx128x16 tiles -----------------
// Template BM in {32, 64}: 8 warps (2m x 4n), warp tile (BM/2) x 32.
// 4-stage cp.async pipeline of RAW f32 tiles; tf32 hi/lo split via LOP3.
// BM=32 doubles the grid for the small GCN/JK GEMMs (grid-limited occupancy).
#define STAGES 4
struct GTask { const float* A; const float* W1; const float* W2; float* C1; float* C2; int M; };

template <int BM>
__global__ __launch_bounds__(256) void k_gemm(
        GTask ta, GTask tb,
        int lda, int Nsplit, int ldw, const float* bias, int ldc, int K) {
    const int MI = BM / 32;                 // m16-tiles per warp (1 or 2)
    __shared__ float As[STAGES][BM][20];    // [m][k] raw f32, pad 4 (LDSM-safe)
    __shared__ float Bs[STAGES][16][136];   // [k][n] raw f32, pad 8 (conflict-free)
    GTask t = (blockIdx.z == 0) ? ta : tb;
    int row0 = blockIdx.y * BM;
    if (row0 >= t.M) return;
    int col0 = blockIdx.x * 128;
    const float* Wb; float* Cb;
    if (col0 < Nsplit) { Wb = t.W1 + col0;            Cb = t.C1 + col0; }
    else               { Wb = t.W2 + (col0 - Nsplit); Cb = t.C2 + (col0 - Nsplit); }

    int tid = threadIdx.x;
    int lane = tid & 31, wid = tid >> 5;
    int warp_m = wid & 1, warp_n = wid >> 1;   // 2m x 4n warp grid
    int g = lane >> 2, tg = lane & 3;
    int mbase = warp_m * (BM / 2), nbase0 = warp_n * 32;

    // copy geometry: A tile BM*4 float4, B tile 512 float4 (2/thread)
    int ar0 = tid >> 2,           ac4 = tid & 3;
    int br0 = tid >> 5,           bc4 = tid & 31;
    uint32_t as_sh[STAGES], bs_sh[STAGES];
    #pragma unroll
    for (int s = 0; s < STAGES; s++) {
        as_sh[s] = (uint32_t)__cvta_generic_to_shared(&As[s][0][0]);
        bs_sh[s] = (uint32_t)__cvta_generic_to_shared(&Bs[s][0][0]);
    }

    // ldmatrix lane geometry (tiles: m+0/m+8 x k+0/k+4)
    int lr = lane & 7, tsel = lane >> 3;
    int arow = ((tsel & 1) << 3) + lr;
    int acol = (tsel >> 1) << 2;

    int ntiles = K / 16;
    auto issue = [&](int tt) {
        int s = tt % STAGES;
        int k0 = tt * 16;
        if (ar0 < BM)
            cpa16(as_sh[s] + ((uint32_t)ar0 * 20 + ac4 * 4) * 4,
                  t.A + (size_t)(row0 + ar0) * lda + k0 + ac4 * 4);
        cpa16(bs_sh[s] + ((uint32_t)br0 * 136 + bc4 * 4) * 4,
              Wb + (size_t)(k0 + br0) * ldw + bc4 * 4);
        cpa16(bs_sh[s] + ((uint32_t)(br0 + 8) * 136 + bc4 * 4) * 4,
              Wb + (size_t)(k0 + br0 + 8) * ldw + bc4 * 4);
        cpa_commit();
    };

    float acc[MI][4][4];
    #pragma unroll
    for (int mi = 0; mi < MI; mi++)
        #pragma unroll
        for (int ni = 0; ni < 4; ni++)
            #pragma unroll
            for (int q = 0; q < 4; q++) acc[mi][ni][q] = 0.f;

    // prologue: 3 tiles in flight (ntiles >= 4 for all call sites)
    issue(0);
    issue(1);
    issue(2);

    for (int tt = 0; tt < ntiles; tt++) {
        int s = tt % STAGES;
        if (tt + 2 < ntiles)      asm volatile("cp.async.wait_group 2;");
        else if (tt + 1 < ntiles) asm volatile("cp.async.wait_group 1;");
        else                      asm volatile("cp.async.wait_group 0;");
        __syncthreads();
        if (tt + 3 < ntiles) issue(tt + 3);   // writes slot (tt-1)%4: safe after sync

        #pragma unroll
        for (int ks = 0; ks < 16; ks += 8) {
            // A raw fragments via ldmatrix, then mask-split hi/lo in registers
            uint32_t ah[MI][4], al[MI][4];
            #pragma unroll
            for (int mi = 0; mi < MI; mi++) {
                uint32_t raw0, raw1, raw2, raw3;
                uint32_t off = ((uint32_t)(mbase + mi * 16 + arow) * 20
                                + (uint32_t)(ks + acol)) * 4;
                ldsm4(raw0, raw1, raw2, raw3, as_sh[s] + off);
                float v0 = __uint_as_float(raw0), v1 = __uint_as_float(raw1);
                float v2 = __uint_as_float(raw2), v3 = __uint_as_float(raw3);
                ah[mi][0] = tfmask(v0); al[mi][0] = tfmask(v0 - __uint_as_float(ah[mi][0]));
                ah[mi][1] = tfmask(v1); al[mi][1] = tfmask(v1 - __uint_as_float(ah[mi][1]));
                ah[mi][2] = tfmask(v2); al[mi][2] = tfmask(v2 - __uint_as_float(ah[mi][2]));
                ah[mi][3] = tfmask(v3); al[mi][3] = tfmask(v3 - __uint_as_float(ah[mi][3]));
            }
            #pragma unroll
            for (int ni = 0; ni < 4; ni++) {
                int n0 = nbase0 + ni * 8;
                float rb0 = Bs[s][ks + tg][n0 + g];
                float rb1 = Bs[s][ks + tg + 4][n0 + g];
                uint32_t bh0 = tfmask(rb0), bl0 = tfmask(rb0 - __uint_as_float(bh0));
                uint32_t bh1 = tfmask(rb1), bl1 = tfmask(rb1 - __uint_as_float(bh1));
                #pragma unroll
                for (int mi = 0; mi < MI; mi++) {
                    mma8(acc[mi][ni], ah[mi], bl0, bl1);   // hi * lo
                    mma8(acc[mi][ni], al[mi], bh0, bh1);   // lo * hi
                    mma8(acc[mi][ni], ah[mi], bh0, bh1);   // hi * hi
                }
            }
        }
        __syncthreads();
    }

    // epilogue: thread owns rows {g, g+8} of each m16 tile, cols {2tg, 2tg+1}
    #pragma unroll
    for (int mi = 0; mi < MI; mi++) {
        int r0 = row0 + mbase + mi * 16 + g;
        #pragma unroll
        for (int ni = 0; ni < 4; ni++) {
            int lc = nbase0 + ni * 8 + tg * 2;
            float b0 = 0.f, b1 = 0.f;
            if (bias) { b0 = bias[col0 + lc]; b1 = bias[col0 + lc + 1]; }
            float* p0 = Cb + (size_t)r0 * ldc + lc;
            float* p1 = p0 + (size_t)8 * ldc;
            *(float2*)p0 = make_float2(acc[mi][ni][0] + b0, acc[mi][ni][1] + b1);
            *(float2*)p1 = make_float2(acc[mi][ni][2] + b0, acc[mi][ni][3] + b1);
        }
    }
}

// ---------------- GCN aggregate, both graphs, 2-edge unrolled -------------
__global__ void k_gcn_agg2(const float* __restrict__ h,
                           const float* __restrict__ bias_m, const float* __restrict__ bias_d,
                           float* __restrict__ out_m, float* __restrict__ out_d,
                           int ldm, int ldd) {
    int w = (blockIdx.x * blockDim.x + threadIdx.x) >> 5;
    int lane = threadIdx.x & 31;
    if (w >= NTOT) return;
    const int* row; const int* src; const float* wcs; const float* bias;
    const float* hb; const float* deg; float* po; int node;
    if (w < N_M) {
        node = w; row = g_row_m; src = g_src_m; wcs = g_w_m; bias = bias_m;
        hb = h; deg = g_deg_m;
        po = out_m + (size_t)w * ldm + lane * 4;
    } else {
        node = w - N_M; row = g_row_d; src = g_src_d; wcs = g_w_d; bias = bias_d;
        hb = h + (size_t)N_M * HID; deg = g_deg_d;
        po = out_d + (size_t)(w - N_M) * ldd + lane * 4;
    }
    int rs = row[node], re = row[node + 1];
    float4 acc = make_float4(0.f, 0.f, 0.f, 0.f);
    int j = rs;
    for (; j + 1 < re; j += 2) {
        int s0 = src[j], s1 = src[j + 1];
        float w0 = wcs[j], w1 = wcs[j + 1];
        float4 v0 = ld4(hb + (size_t)s0 * HID + lane * 4);
        float4 v1 = ld4(hb + (size_t)s1 * HID + lane * 4);
        acc.x += w0 * v0.x + w1 * v1.x; acc.y += w0 * v0.y + w1 * v1.y;
        acc.z += w0 * v0.z + w1 * v1.z; acc.w += w0 * v0.w + w1 * v1.w;
    }
    if (j < re) {
        int s0 = src[j];
        float w0 = wcs[j];
        float4 v0 = ld4(hb + (size_t)s0 * HID + lane * 4);
        acc.x += w0 * v0.x; acc.y += w0 * v0.y; acc.z += w0 * v0.z; acc.w += w0 * v0.w;
    }
    float di = rsqrtf(deg[node]);
    float sw = di * di;
    float4 v = ld4(hb + (size_t)node * HID + lane * 4);
    acc.x += sw * v.x; acc.y += sw * v.y; acc.z += sw * v.z; acc.w += sw * v.w;
    float4 b = ld4(bias + lane * 4);
    acc.x = fmaxf(acc.x + b.x, 0.f); acc.y = fmaxf(acc.y + b.y, 0.f);
    acc.z = fmaxf(acc.z + b.z, 0.f); acc.w = fmaxf(acc.w + b.w, 0.f);
    *(float4*)po = acc;
}

// ---------------- Fused GATv2 (warp per dst, 2-edge unrolled) -------------
template <int HC>
__global__ void k_gat_fused(const float* __restrict__ xl, const float* __restrict__ xr,
                            const float* __restrict__ att,
                            const float* __restrict__ bias,
                            float* __restrict__ out, int ldout, int elu) {
    const int CH = HC / 32;
    int i = (blockIdx.x * blockDim.x + threadIdx.x) >> 5;
    int lane = threadIdx.x & 31;
    if (i >= NTOT) return;
    int rs = g_row_g[i], re = g_row_g[i + 1];

    float attv[CH], xrv[CH];
    #pragma unroll
    for (int k = 0; k < CH; k += 4) {
        float4 a = ld4(att + lane * CH + k);
        attv[k] = a.x; attv[k + 1] = a.y; attv[k + 2] = a.z; attv[k + 3] = a.w;
        float4 r = ld4(xr + (size_t)i * HC + lane * CH + k);
        xrv[k] = r.x; xrv[k + 1] = r.y; xrv[k + 2] = r.z; xrv[k + 3] = r.w;
    }

    float m = -1e30f, den = 0.f;
    float num[CH];
    #pragma unroll
    for (int k = 0; k < CH; k++) num[k] = 0.f;

    int j = rs;
    for (; j + 1 < re; j += 2) {
        int s0 = g_src_g[j], s1 = g_src_g[j + 1];
        float xlv0[CH], xlv1[CH];
        #pragma unroll
        for (int k = 0; k < CH; k += 4) {
            float4 v0 = ld4(xl + (size_t)s0 * HC + lane * CH + k);
            xlv0[k] = v0.x; xlv0[k + 1] = v0.y; xlv0[k + 2] = v0.z; xlv0[k + 3] = v0.w;
            float4 v1 = ld4(xl + (size_t)s1 * HC + lane * CH + k);
            xlv1[k] = v1.x; xlv1[k + 1] = v1.y; xlv1[k + 2] = v1.z; xlv1[k + 3] = v1.w;
        }
        float p0 = 0.f, p1 = 0.f;
        #pragma unroll
        for (int k = 0; k < CH; k++) {
            float t0 = xlv0[k] + xrv[k];
            t0 = t0 > 0.f ? t0 : 0.2f * t0;
            p0 += t0 * attv[k];
            float t1 = xlv1[k] + xrv[k];
            t1 = t1 > 0.f ? t1 : 0.2f * t1;
            p1 += t1 * attv[k];
        }
        p0 += __shfl_xor_sync(0xffffffffu, p0, 1);
        p1 += __shfl_xor_sync(0xffffffffu, p1, 1);
        p0 += __shfl_xor_sync(0xffffffffu, p0, 2);
        p1 += __shfl_xor_sync(0xffffffffu, p1, 2);
        p0 += __shfl_xor_sync(0xffffffffu, p0, 4);
        p1 += __shfl_xor_sync(0xffffffffu, p1, 4);
        float mn = fmaxf(m, p0);
        float c  = expf(m - mn);
        float ex = expf(p0 - mn);
        den = den * c + ex;
        #pragma unroll
        for (int k = 0; k < CH; k++) num[k] = num[k] * c + ex * xlv0[k];
        m = mn;
        mn = fmaxf(m, p1);
        c  = expf(m - mn);
        ex = expf(p1 - mn);
        den = den * c + ex;
        #pragma unroll
        for (int k = 0; k < CH; k++) num[k] = num[k] * c + ex * xlv1[k];
        m = mn;
    }
    if (j < re) {
        int s0 = g_src_g[j];
        float xlv0[CH];
        float p0 = 0.f;
        #pragma unroll
        for (int k = 0; k < CH; k += 4) {
            float4 v0 = ld4(xl + (size_t)s0 * HC + lane * CH + k);
            xlv0[k] = v0.x; xlv0[k + 1] = v0.y; xlv0[k + 2] = v0.z; xlv0[k + 3] = v0.w;
        }
        #pragma unroll
        for (int k = 0; k < CH; k++) {
            float t0 = xlv0[k] + xrv[k];
            t0 = t0 > 0.f ? t0 : 0.2f * t0;
            p0 += t0 * attv[k];
        }
        p0 += __shfl_xor_sync(0xffffffffu, p0, 1);
        p0 += __shfl_xor_sync(0xffffffffu, p0, 2);
        p0 += __shfl_xor_sync(0xffffffffu, p0, 4);
        float mn = fmaxf(m, p0);
        float c  = expf(m - mn);
        float ex = expf(p0 - mn);
        den = den * c + ex;
        #pragma unroll
        for (int k = 0; k < CH; k++) num[k] = num[k] * c + ex * xlv0[k];
        m = mn;
    }

    float inv = 0.25f / den;   // includes 1/H head-mean
    #pragma unroll
    for (int k = 0; k < CH; k++) {
        float v = num[k] * inv;
        v += __shfl_xor_sync(0xffffffffu, v, 8);
        v += __shfl_xor_sync(0xffffffffu, v, 16);
        num[k] = v;
    }
    if (lane < 8) {
        float o[CH];
        #pragma unroll
        for (int k = 0; k < CH; k++) {
            float v = num[k] + bias[lane * CH + k];
            if (elu) v = v > 0.f ? v : expm1f(v);
            o[k] = v;
        }
        float* po = out + (size_t)i * ldout + lane * CH;
        #pragma unroll
        for (int k = 0; k < CH; k += 4)
            *(float4*)(po + k) = make_float4(o[k], o[k + 1], o[k + 2], o[k + 3]);
    }
}

// ---------------- host orchestration ----------------
extern "C" void kernel_launch(void* const* d_in, const int* in_sizes, int n_in,
                              void* d_out, int out_size) {
    const float* mm_f = (const float*)d_in[0];
    const float* d_s  = (const float*)d_in[1];
    const float* msM  = (const float*)d_in[2];
    const float* dsM  = (const float*)d_in[3];
    const int*   e_mm = (const int*)d_in[4];
    const int*   e_dd = (const int*)d_in[5];
    const int*   e_g  = (const int*)d_in[6];
    const float* W_m1 = (const float*)d_in[7];  const float* b_m1 = (const float*)d_in[8];
    const float* W_m2 = (const float*)d_in[9];  const float* b_m2 = (const float*)d_in[10];
    const float* W_d1 = (const float*)d_in[11]; const float* b_d1 = (const float*)d_in[12];
    const float* W_d2 = (const float*)d_in[13]; const float* b_d2 = (const float*)d_in[14];
    const float* Wl1  = (const float*)d_in[15]; const float* Wr1  = (const float*)d_in[16];
    const float* att1 = (const float*)d_in[17]; const float* bias1 = (const float*)d_in[18];
    const float* Wl2  = (const float*)d_in[19]; const float* Wr2  = (const float*)d_in[20];
    const float* att2 = (const float*)d_in[21]; const float* bias2 = (const float*)d_in[22];
    const float* Wjk  = (const float*)d_in[23]; const float* bjk  = (const float*)d_in[24];
    float* out = (float*)d_out;

    float *p_A, *p_B, *p_tmp, *p_xjk;
    cudaGetSymbolAddress((void**)&p_A,   g_bufA);
    cudaGetSymbolAddress((void**)&p_B,   g_bufB);
    cudaGetSymbolAddress((void**)&p_tmp, g_tmp);
    cudaGetSymbolAddress((void**)&p_xjk, g_xjk);

    const int GB = TPB;
    auto blk = [](int n) { return (n + TPB - 1) / TPB; };
    auto wblk = [](int nwarps) { return (nwarps * 32 + TPB - 1) / TPB; };

    // ---- prep + GCN layer1 GEMM (gemm at ncu slot #4) ----
    k_init<<<blk(NTOT), GB>>>();
    k_prep_all<<<blk(E_MM + E_DD + E_G), GB>>>(e_mm, msM, e_dd, dsM, e_g);
    k_scan3<<<3, 1024>>>();
    {
        GTask ta = { mm_f, W_m1, W_m1, p_A,                      p_A,                      N_M };
        GTask tb = { d_s,  W_d1, W_d1, p_A + (size_t)N_M * HID,  p_A + (size_t)N_M * HID,  N_D };
        k_gemm<32><<<dim3(1, N_M / 32, 2), 256>>>(ta, tb, HID, 128, HID, nullptr, HID, HID);
    }
    k_fill_all<<<blk(E_MM + E_DD + E_G + NTOT), GB>>>(e_mm, e_dd, e_g);

    // ---- GCN layer 1 aggregate ----
    k_gcn_agg2<<<wblk(NTOT), GB>>>(p_A, b_m1, b_d1, p_tmp, p_tmp + (size_t)N_M * HID, HID, HID);

    // ---- GCN layer 2 ----
    {
        GTask ta = { p_tmp,                      W_m2, W_m2, p_A,                     p_A,                     N_M };
        GTask tb = { p_tmp + (size_t)N_M * HID,  W_d2, W_d2, p_A + (size_t)N_M * HID, p_A + (size_t)N_M * HID, N_D };
        k_gemm<32><<<dim3(1, N_M / 32, 2), 256>>>(ta, tb, HID, 128, HID, nullptr, HID, HID);
    }
    // x0 = relu(gcn2) into xjk cols [0,128)
    k_gcn_agg2<<<wblk(NTOT), GB>>>(p_A, b_m2, b_d2, p_xjk, p_xjk + (size_t)N_M * 224, 224, 224);

    // ---- GATv2 layer 1: xl|xr in ONE dual-W GEMM (K=128, Nc=256+256) ----
    {
        GTask ta = { p_xjk, Wl1, Wr1, p_A, p_B, NTOT };
        k_gemm<64><<<dim3(4, NTOT / 64, 1), 256>>>(ta, ta, 224, 256, 256, nullptr, 256, 128);
    }
    k_gat_fused<256><<<wblk(NTOT), GB>>>(p_A, p_B, att1, bias1, p_xjk + 128, 224, 1);

    // ---- GATv2 layer 2 (K=64, Nc=128+128) ----
    {
        GTask ta = { p_xjk + 128, Wl2, Wr2, p_A, p_B, NTOT };
        k_gemm<32><<<dim3(2, NTOT / 32, 1), 256>>>(ta, ta, 224, 128, 128, nullptr, 128, 64);
    }
    k_gat_fused<128><<<wblk(NTOT), GB>>>(p_A, p_B, att2, bias2, p_xjk + 192, 224, 0);

    // ---- JumpingKnowledge linear: out = [x0|x1|x2] @ Wjk + bjk ----
    {
        GTask ta = { p_xjk, Wjk, Wjk, out, out, NTOT };
        k_gemm<32><<<dim3(1, NTOT / 32, 1), 256>>>(ta, ta, 224, 128, 128, bjk, 128, 224);
    }
}

// round 17
// speedup vs baseline: 1.0966x; 1.0966x over previous
#include <cuda_runtime.h>
#include <math.h>
#include <stdint.h>

// ---------------- problem constants (fixed by the dataset) ----------------
#define N_M   8192
#define N_D   6144
#define NTOT  14336            // N_M + N_D
#define E_MM  131072
#define E_DD  98304
#define E_G   229376
#define EG_TOT (E_G + NTOT)    // real edges + self loops = 243712
#define HID   128
#define TPB   256

// ---------------- scratch (static device globals; no runtime alloc) -------
__device__ float g_ew_m[E_MM];
__device__ float g_ew_d[E_DD];
__device__ float g_deg_m[N_M];
__device__ float g_deg_d[N_D];
__device__ int   g_cnt_m[N_M],  g_row_m[N_M + 1],  g_cur_m[N_M];
__device__ int   g_src_m[E_MM];  __device__ float g_w_m[E_MM];
__device__ int   g_cnt_d[N_D],  g_row_d[N_D + 1],  g_cur_d[N_D];
__device__ int   g_src_d[E_DD];  __device__ float g_w_d[E_DD];
__device__ int   g_cnt_g[NTOT], g_row_g[NTOT + 1], g_cur_g[NTOT];
__device__ int   g_src_g[EG_TOT];
__device__ float g_bufA[(size_t)NTOT * 256];
__device__ float g_bufB[(size_t)NTOT * 256];
__device__ float g_tmp [(size_t)NTOT * 128];
__device__ float g_xjk [(size_t)NTOT * 224];

__device__ __forceinline__ float4 ld4(const float* p) { return *(const float4*)p; }

// tf32 split via mantissa mask (full-rate LOP3 instead of quarter-rate CVT).
__device__ __forceinline__ uint32_t tfmask(float x) {
    return __float_as_uint(x) & 0xFFFFE000u;
}

// one m16n8k8 tf32 mma, D += A*B (D==C in-place)
__device__ __forceinline__ void mma8(float* d, const uint32_t* a, uint32_t b0, uint32_t b1) {
    asm("mma.sync.aligned.m16n8k8.row.col.f32.tf32.tf32.f32 "
        "{%0,%1,%2,%3}, {%4,%5,%6,%7}, {%8,%9}, {%0,%1,%2,%3};"
        : "+f"(d[0]), "+f"(d[1]), "+f"(d[2]), "+f"(d[3])
        : "r"(a[0]), "r"(a[1]), "r"(a[2]), "r"(a[3]), "r"(b0), "r"(b1));
}

// ldmatrix x4 (b16 form; four 8x4-of-b32 tiles for tf32 fragments)
__device__ __forceinline__ void ldsm4(uint32_t& r0, uint32_t& r1, uint32_t& r2,
                                      uint32_t& r3, uint32_t addr) {
    asm volatile("ldmatrix.sync.aligned.m8n8.x4.shared.b16 {%0,%1,%2,%3}, [%4];"
        : "=r"(r0), "=r"(r1), "=r"(r2), "=r"(r3) : "r"(addr));
}

// cp.async 16B global->shared
__device__ __forceinline__ void cpa16(uint32_t dst, const float* src) {
    asm volatile("cp.async.cg.shared.global [%0], [%1], 16;" :: "r"(dst), "l"(src));
}
__device__ __forceinline__ void cpa_commit() {
    asm volatile("cp.async.commit_group;");
}

// ---------------- init ----------------
__global__ void k_init() {
    int i = blockIdx.x * blockDim.x + threadIdx.x;
    if (i < N_M)  { g_deg_m[i] = 1.0f; g_cnt_m[i] = 0; }   // self-loop weight 1
    if (i < N_D)  { g_deg_d[i] = 1.0f; g_cnt_d[i] = 0; }
    if (i < NTOT) { g_cnt_g[i] = 1; }                       // self loop pre-counted
}

// ---------------- combined edge prep (both GCN graphs + GAT count) --------
__global__ void k_prep_all(const int* __restrict__ e_mm, const float* __restrict__ msM,
                           const int* __restrict__ e_dd, const float* __restrict__ dsM,
                           const int* __restrict__ e_g) {
    int i = blockIdx.x * blockDim.x + threadIdx.x;
    if (i < E_MM) {
        int s = e_mm[i], d = e_mm[E_MM + i];
        float w = msM[(size_t)s * N_M + d];
        g_ew_m[i] = w;
        atomicAdd(&g_deg_m[d], w);
        atomicAdd(&g_cnt_m[d], 1);
    } else if (i < E_MM + E_DD) {
        int f = i - E_MM;
        int s = e_dd[f], d = e_dd[E_DD + f];
        float w = dsM[(size_t)s * N_D + d];
        g_ew_d[f] = w;
        atomicAdd(&g_deg_d[d], w);
        atomicAdd(&g_cnt_d[d], 1);
    } else if (i < E_MM + E_DD + E_G) {
        int f = i - E_MM - E_DD;
        atomicAdd(&g_cnt_g[e_g[E_G + f]], 1);
    }
}

// ---------------- 3 scans in one launch (blockIdx picks the graph) --------
__global__ void k_scan3() {
    __shared__ int sh[1024];
    const int* cnt; int* row; int* cur; int n;
    if (blockIdx.x == 0)      { cnt = g_cnt_m; row = g_row_m; cur = g_cur_m; n = N_M; }
    else if (blockIdx.x == 1) { cnt = g_cnt_d; row = g_row_d; cur = g_cur_d; n = N_D; }
    else                      { cnt = g_cnt_g; row = g_row_g; cur = g_cur_g; n = NTOT; }
    int t = threadIdx.x;
    int chunk = (n + 1023) / 1024;
    int lo = t * chunk, hi = min(lo + chunk, n);
    int sum = 0;
    for (int i = lo; i < hi; i++) sum += cnt[i];
    sh[t] = sum;
    __syncthreads();
    for (int off = 1; off < 1024; off <<= 1) {
        int v = 0;
        if (t >= off) v = sh[t - off];
        __syncthreads();
        if (t >= off) sh[t] += v;
        __syncthreads();
    }
    int run = (t == 0) ? 0 : sh[t - 1];
    for (int i = lo; i < hi; i++) { row[i] = run; cur[i] = run; run += cnt[i]; }
    if (t == 1023) row[n] = sh[1023];
}

// ---------------- combined CSR fill; GCN norm computed inline -------------
__global__ void k_fill_all(const int* __restrict__ e_mm, const int* __restrict__ e_dd,
                           const int* __restrict__ e_g) {
    int i = blockIdx.x * blockDim.x + threadIdx.x;
    if (i < E_MM) {
        int s = e_mm[i], d = e_mm[E_MM + i];
        int p = atomicAdd(&g_cur_m[d], 1);
        g_src_m[p] = s;
        g_w_m[p] = rsqrtf(g_deg_m[s]) * g_ew_m[i] * rsqrtf(g_deg_m[d]);
    } else if (i < E_MM + E_DD) {
        int f = i - E_MM;
        int s = e_dd[f], d = e_dd[E_DD + f];
        int p = atomicAdd(&g_cur_d[d], 1);
        g_src_d[p] = s;
        g_w_d[p] = rsqrtf(g_deg_d[s]) * g_ew_d[f] * rsqrtf(g_deg_d[d]);
    } else if (i < E_MM + E_DD + E_G) {
        int f = i - E_MM - E_DD;
        int d = e_g[E_G + f];
        int p = atomicAdd(&g_cur_g[d], 1);
        g_src_g[p] = e_g[f];
    } else if (i < E_MM + E_DD + E_G + NTOT) {
        int f = i - E_MM - E_DD - E_G;     // self loop
        int p = atomicAdd(&g_cur_g[f], 1);
        g_src_g[p] = f;
    }
}

// ---------------- tf32x3 tensor-core GEMM: 64x128x16 tiles -----------------
// 8 warps (2m x 4n), warp tile m32 x n32, mma.m16n8k8.tf32, 3-pass comp.
// 4-stage cp.async pipeline of RAW f32 tiles; tf32 hi/lo split via LOP3.
// (R15 config — BM=64 amortizes per-warp B overhead; BM=32 regressed.)
#define STAGES 4
struct GTask { const float* A; const float* W1; const float* W2; float* C1; float* C2; int M; };

__global__ __launch_bounds__(256) void k_gemm(
        GTask ta, GTask tb,
        int lda, int Nsplit, int ldw, const float* bias, int ldc, int K) {
    __shared__ float As[STAGES][64][20];    // [m][k] raw f32, pad 4 (LDSM-safe)
    __shared__ float Bs[STAGES][16][136];   // [k][n] raw f32, pad 8 (conflict-free)
    GTask t = (blockIdx.z == 0) ? ta : tb;
    int row0 = blockIdx.y * 64;
    if (row0 >= t.M) return;
    int col0 = blockIdx.x * 128;
    const float* Wb; float* Cb;
    if (col0 < Nsplit) { Wb = t.W1 + col0;            Cb = t.C1 + col0; }
    else               { Wb = t.W2 + (col0 - Nsplit); Cb = t.C2 + (col0 - Nsplit); }

    int tid = threadIdx.x;
    int lane = tid & 31, wid = tid >> 5;
    int warp_m = wid & 1, warp_n = wid >> 1;   // 2m x 4n warp grid
    int g = lane >> 2, tg = lane & 3;
    int mbase = warp_m * 32, nbase0 = warp_n * 32;

    int ar0 = tid >> 2,           ac4 = tid & 3;
    int br0 = tid >> 5,           bc4 = tid & 31;
    uint32_t as_sh[STAGES], bs_sh[STAGES];
    #pragma unroll
    for (int s = 0; s < STAGES; s++) {
        as_sh[s] = (uint32_t)__cvta_generic_to_shared(&As[s][0][0]);
        bs_sh[s] = (uint32_t)__cvta_generic_to_shared(&Bs[s][0][0]);
    }

    int lr = lane & 7, tsel = lane >> 3;
    int arow = ((tsel & 1) << 3) + lr;
    int acol = (tsel >> 1) << 2;

    int ntiles = K / 16;
    auto issue = [&](int tt) {
        int s = tt % STAGES;
        int k0 = tt * 16;
        cpa16(as_sh[s] + ((uint32_t)ar0 * 20 + ac4 * 4) * 4,
              t.A + (size_t)(row0 + ar0) * lda + k0 + ac4 * 4);
        cpa16(bs_sh[s] + ((uint32_t)br0 * 136 + bc4 * 4) * 4,
              Wb + (size_t)(k0 + br0) * ldw + bc4 * 4);
        cpa16(bs_sh[s] + ((uint32_t)(br0 + 8) * 136 + bc4 * 4) * 4,
              Wb + (size_t)(k0 + br0 + 8) * ldw + bc4 * 4);
        cpa_commit();
    };

    float acc[2][4][4];
    #pragma unroll
    for (int mi = 0; mi < 2; mi++)
        #pragma unroll
        for (int ni = 0; ni < 4; ni++)
            #pragma unroll
            for (int q = 0; q < 4; q++) acc[mi][ni][q] = 0.f;

    issue(0);
    issue(1);
    issue(2);

    for (int tt = 0; tt < ntiles; tt++) {
        int s = tt % STAGES;
        if (tt + 2 < ntiles)      asm volatile("cp.async.wait_group 2;");
        else if (tt + 1 < ntiles) asm volatile("cp.async.wait_group 1;");
        else                      asm volatile("cp.async.wait_group 0;");
        __syncthreads();
        if (tt + 3 < ntiles) issue(tt + 3);   // writes slot (tt-1)%4: safe after sync

        #pragma unroll
        for (int ks = 0; ks < 16; ks += 8) {
            uint32_t ah[2][4], al[2][4];
            #pragma unroll
            for (int mi = 0; mi < 2; mi++) {
                uint32_t raw0, raw1, raw2, raw3;
                uint32_t off = ((uint32_t)(mbase + mi * 16 + arow) * 20
                                + (uint32_t)(ks + acol)) * 4;
                ldsm4(raw0, raw1, raw2, raw3, as_sh[s] + off);
                float v0 = __uint_as_float(raw0), v1 = __uint_as_float(raw1);
                float v2 = __uint_as_float(raw2), v3 = __uint_as_float(raw3);
                ah[mi][0] = tfmask(v0); al[mi][0] = tfmask(v0 - __uint_as_float(ah[mi][0]));
                ah[mi][1] = tfmask(v1); al[mi][1] = tfmask(v1 - __uint_as_float(ah[mi][1]));
                ah[mi][2] = tfmask(v2); al[mi][2] = tfmask(v2 - __uint_as_float(ah[mi][2]));
                ah[mi][3] = tfmask(v3); al[mi][3] = tfmask(v3 - __uint_as_float(ah[mi][3]));
            }
            #pragma unroll
            for (int ni = 0; ni < 4; ni++) {
                int n0 = nbase0 + ni * 8;
                float rb0 = Bs[s][ks + tg][n0 + g];
                float rb1 = Bs[s][ks + tg + 4][n0 + g];
                uint32_t bh0 = tfmask(rb0), bl0 = tfmask(rb0 - __uint_as_float(bh0));
                uint32_t bh1 = tfmask(rb1), bl1 = tfmask(rb1 - __uint_as_float(bh1));
                #pragma unroll
                for (int mi = 0; mi < 2; mi++) {
                    mma8(acc[mi][ni], ah[mi], bl0, bl1);   // hi * lo
                    mma8(acc[mi][ni], al[mi], bh0, bh1);   // lo * hi
                    mma8(acc[mi][ni], ah[mi], bh0, bh1);   // hi * hi
                }
            }
        }
        __syncthreads();
    }

    #pragma unroll
    for (int mi = 0; mi < 2; mi++) {
        int r0 = row0 + mbase + mi * 16 + g;
        #pragma unroll
        for (int ni = 0; ni < 4; ni++) {
            int lc = nbase0 + ni * 8 + tg * 2;
            float b0 = 0.f, b1 = 0.f;
            if (bias) { b0 = bias[col0 + lc]; b1 = bias[col0 + lc + 1]; }
            float* p0 = Cb + (size_t)r0 * ldc + lc;
            float* p1 = p0 + (size_t)8 * ldc;
            *(float2*)p0 = make_float2(acc[mi][ni][0] + b0, acc[mi][ni][1] + b1);
            *(float2*)p1 = make_float2(acc[mi][ni][2] + b0, acc[mi][ni][3] + b1);
        }
    }
}

// ---------------- GCN aggregate, both graphs, 4-edge unrolled -------------
__global__ void k_gcn_agg2(const float* __restrict__ h,
                           const float* __restrict__ bias_m, const float* __restrict__ bias_d,
                           float* __restrict__ out_m, float* __restrict__ out_d,
                           int ldm, int ldd) {
    int w = (blockIdx.x * blockDim.x + threadIdx.x) >> 5;
    int lane = threadIdx.x & 31;
    if (w >= NTOT) return;
    const int* row; const int* src; const float* wcs; const float* bias;
    const float* hb; const float* deg; float* po; int node;
    if (w < N_M) {
        node = w; row = g_row_m; src = g_src_m; wcs = g_w_m; bias = bias_m;
        hb = h; deg = g_deg_m;
        po = out_m + (size_t)w * ldm + lane * 4;
    } else {
        node = w - N_M; row = g_row_d; src = g_src_d; wcs = g_w_d; bias = bias_d;
        hb = h + (size_t)N_M * HID; deg = g_deg_d;
        po = out_d + (size_t)(w - N_M) * ldd + lane * 4;
    }
    int rs = row[node], re = row[node + 1];
    float4 acc = make_float4(0.f, 0.f, 0.f, 0.f);
    int j = rs;
    for (; j + 3 < re; j += 4) {
        int s0 = src[j], s1 = src[j + 1], s2 = src[j + 2], s3 = src[j + 3];
        float w0 = wcs[j], w1 = wcs[j + 1], w2 = wcs[j + 2], w3 = wcs[j + 3];
        float4 v0 = ld4(hb + (size_t)s0 * HID + lane * 4);
        float4 v1 = ld4(hb + (size_t)s1 * HID + lane * 4);
        float4 v2 = ld4(hb + (size_t)s2 * HID + lane * 4);
        float4 v3 = ld4(hb + (size_t)s3 * HID + lane * 4);
        acc.x += w0 * v0.x + w1 * v1.x + w2 * v2.x + w3 * v3.x;
        acc.y += w0 * v0.y + w1 * v1.y + w2 * v2.y + w3 * v3.y;
        acc.z += w0 * v0.z + w1 * v1.z + w2 * v2.z + w3 * v3.z;
        acc.w += w0 * v0.w + w1 * v1.w + w2 * v2.w + w3 * v3.w;
    }
    for (; j < re; j++) {
        int s0 = src[j];
        float w0 = wcs[j];
        float4 v0 = ld4(hb + (size_t)s0 * HID + lane * 4);
        acc.x += w0 * v0.x; acc.y += w0 * v0.y; acc.z += w0 * v0.z; acc.w += w0 * v0.w;
    }
    float di = rsqrtf(deg[node]);
    float sw = di * di;
    float4 v = ld4(hb + (size_t)node * HID + lane * 4);
    acc.x += sw * v.x; acc.y += sw * v.y; acc.z += sw * v.z; acc.w += sw * v.w;
    float4 b = ld4(bias + lane * 4);
    acc.x = fmaxf(acc.x + b.x, 0.f); acc.y = fmaxf(acc.y + b.y, 0.f);
    acc.z = fmaxf(acc.z + b.z, 0.f); acc.w = fmaxf(acc.w + b.w, 0.f);
    *(float4*)po = acc;
}

// ---------------- Fused GATv2 (warp per dst, 4-edge joint-max blocks) -----
template <int HC>
__global__ void k_gat_fused(const float* __restrict__ xl, const float* __restrict__ xr,
                            const float* __restrict__ att,
                            const float* __restrict__ bias,
                            float* __restrict__ out, int ldout, int elu) {
    const int CH = HC / 32;
    int i = (blockIdx.x * blockDim.x + threadIdx.x) >> 5;
    int lane = threadIdx.x & 31;
    if (i >= NTOT) return;
    int rs = g_row_g[i], re = g_row_g[i + 1];

    float attv[CH], xrv[CH];
    #pragma unroll
    for (int k = 0; k < CH; k += 4) {
        float4 a = ld4(att + lane * CH + k);
        attv[k] = a.x; attv[k + 1] = a.y; attv[k + 2] = a.z; attv[k + 3] = a.w;
        float4 r = ld4(xr + (size_t)i * HC + lane * CH + k);
        xrv[k] = r.x; xrv[k + 1] = r.y; xrv[k + 2] = r.z; xrv[k + 3] = r.w;
    }

    float m = -1e30f, den = 0.f;
    float num[CH];
    #pragma unroll
    for (int k = 0; k < CH; k++) num[k] = 0.f;

    int j = rs;
    // 4-edge blocks: joint max -> one rescale + 4 accumulate terms
    for (; j + 3 < re; j += 4) {
        int s0 = g_src_g[j], s1 = g_src_g[j + 1];
        int s2 = g_src_g[j + 2], s3 = g_src_g[j + 3];
        float xv[4][CH];
        #pragma unroll
        for (int k = 0; k < CH; k += 4) {
            float4 v0 = ld4(xl + (size_t)s0 * HC + lane * CH + k);
            float4 v1 = ld4(xl + (size_t)s1 * HC + lane * CH + k);
            float4 v2 = ld4(xl + (size_t)s2 * HC + lane * CH + k);
            float4 v3 = ld4(xl + (size_t)s3 * HC + lane * CH + k);
            xv[0][k] = v0.x; xv[0][k + 1] = v0.y; xv[0][k + 2] = v0.z; xv[0][k + 3] = v0.w;
            xv[1][k] = v1.x; xv[1][k + 1] = v1.y; xv[1][k + 2] = v1.z; xv[1][k + 3] = v1.w;
            xv[2][k] = v2.x; xv[2][k + 1] = v2.y; xv[2][k + 2] = v2.z; xv[2][k + 3] = v2.w;
            xv[3][k] = v3.x; xv[3][k + 1] = v3.y; xv[3][k + 2] = v3.z; xv[3][k + 3] = v3.w;
        }
        float p[4] = {0.f, 0.f, 0.f, 0.f};
        #pragma unroll
        for (int e = 0; e < 4; e++) {
            #pragma unroll
            for (int k = 0; k < CH; k++) {
                float t = xv[e][k] + xrv[k];
                t = t > 0.f ? t : 0.2f * t;
                p[e] += t * attv[k];
            }
        }
        #pragma unroll
        for (int e = 0; e < 4; e++) {
            p[e] += __shfl_xor_sync(0xffffffffu, p[e], 1);
            p[e] += __shfl_xor_sync(0xffffffffu, p[e], 2);
            p[e] += __shfl_xor_sync(0xffffffffu, p[e], 4);
        }
        float mn = fmaxf(fmaxf(fmaxf(m, p[0]), fmaxf(p[1], p[2])), p[3]);
        float c = expf(m - mn);
        float e0 = expf(p[0] - mn), e1 = expf(p[1] - mn);
        float e2 = expf(p[2] - mn), e3 = expf(p[3] - mn);
        den = den * c + e0 + e1 + e2 + e3;
        #pragma unroll
        for (int k = 0; k < CH; k++)
            num[k] = num[k] * c + e0 * xv[0][k] + e1 * xv[1][k]
                                + e2 * xv[2][k] + e3 * xv[3][k];
        m = mn;
    }
    // tail: single edges
    for (; j < re; j++) {
        int s0 = g_src_g[j];
        float xlv0[CH];
        float p0 = 0.f;
        #pragma unroll
        for (int k = 0; k < CH; k += 4) {
            float4 v0 = ld4(xl + (size_t)s0 * HC + lane * CH + k);
            xlv0[k] = v0.x; xlv0[k + 1] = v0.y; xlv0[k + 2] = v0.z; xlv0[k + 3] = v0.w;
        }
        #pragma unroll
        for (int k = 0; k < CH; k++) {
            float t0 = xlv0[k] + xrv[k];
            t0 = t0 > 0.f ? t0 : 0.2f * t0;
            p0 += t0 * attv[k];
        }
        p0 += __shfl_xor_sync(0xffffffffu, p0, 1);
        p0 += __shfl_xor_sync(0xffffffffu, p0, 2);
        p0 += __shfl_xor_sync(0xffffffffu, p0, 4);
        float mn = fmaxf(m, p0);
        float c  = expf(m - mn);
        float ex = expf(p0 - mn);
        den = den * c + ex;
        #pragma unroll
        for (int k = 0; k < CH; k++) num[k] = num[k] * c + ex * xlv0[k];
        m = mn;
    }

    float inv = 0.25f / den;   // includes 1/H head-mean
    #pragma unroll
    for (int k = 0; k < CH; k++) {
        float v = num[k] * inv;
        v += __shfl_xor_sync(0xffffffffu, v, 8);
        v += __shfl_xor_sync(0xffffffffu, v, 16);
        num[k] = v;
    }
    if (lane < 8) {
        float o[CH];
        #pragma unroll
        for (int k = 0; k < CH; k++) {
            float v = num[k] + bias[lane * CH + k];
            if (elu) v = v > 0.f ? v : expm1f(v);
            o[k] = v;
        }
        float* po = out + (size_t)i * ldout + lane * CH;
        #pragma unroll
        for (int k = 0; k < CH; k += 4)
            *(float4*)(po + k) = make_float4(o[k], o[k + 1], o[k + 2], o[k + 3]);
    }
}

// ---------------- host orchestration ----------------
extern "C" void kernel_launch(void* const* d_in, const int* in_sizes, int n_in,
                              void* d_out, int out_size) {
    const float* mm_f = (const float*)d_in[0];
    const float* d_s  = (const float*)d_in[1];
    const float* msM  = (const float*)d_in[2];
    const float* dsM  = (const float*)d_in[3];
    const int*   e_mm = (const int*)d_in[4];
    const int*   e_dd = (const int*)d_in[5];
    const int*   e_g  = (const int*)d_in[6];
    const float* W_m1 = (const float*)d_in[7];  const float* b_m1 = (const float*)d_in[8];
    const float* W_m2 = (const float*)d_in[9];  const float* b_m2 = (const float*)d_in[10];
    const float* W_d1 = (const float*)d_in[11]; const float* b_d1 = (const float*)d_in[12];
    const float* W_d2 = (const float*)d_in[13]; const float* b_d2 = (const float*)d_in[14];
    const float* Wl1  = (const float*)d_in[15]; const float* Wr1  = (const float*)d_in[16];
    const float* att1 = (const float*)d_in[17]; const float* bias1 = (const float*)d_in[18];
    const float* Wl2  = (const float*)d_in[19]; const float* Wr2  = (const float*)d_in[20];
    const float* att2 = (const float*)d_in[21]; const float* bias2 = (const float*)d_in[22];
    const float* Wjk  = (const float*)d_in[23]; const float* bjk  = (const float*)d_in[24];
    float* out = (float*)d_out;

    float *p_A, *p_B, *p_tmp, *p_xjk;
    cudaGetSymbolAddress((void**)&p_A,   g_bufA);
    cudaGetSymbolAddress((void**)&p_B,   g_bufB);
    cudaGetSymbolAddress((void**)&p_tmp, g_tmp);
    cudaGetSymbolAddress((void**)&p_xjk, g_xjk);

    const int GB = TPB;
    auto blk = [](int n) { return (n + TPB - 1) / TPB; };
    auto wblk = [](int nwarps) { return (nwarps * 32 + TPB - 1) / TPB; };

    // ---- prep + GCN layer1 GEMM (gemm at ncu slot #4) ----
    k_init<<<blk(NTOT), GB>>>();
    k_prep_all<<<blk(E_MM + E_DD + E_G), GB>>>(e_mm, msM, e_dd, dsM, e_g);
    k_scan3<<<3, 1024>>>();
    {
        GTask ta = { mm_f, W_m1, W_m1, p_A,                      p_A,                      N_M };
        GTask tb = { d_s,  W_d1, W_d1, p_A + (size_t)N_M * HID,  p_A + (size_t)N_M * HID,  N_D };
        k_gemm<<<dim3(1, N_M / 64, 2), 256>>>(ta, tb, HID, 128, HID, nullptr, HID, HID);
    }
    k_fill_all<<<blk(E_MM + E_DD + E_G + NTOT), GB>>>(e_mm, e_dd, e_g);

    // ---- GCN layer 1 aggregate ----
    k_gcn_agg2<<<wblk(NTOT), GB>>>(p_A, b_m1, b_d1, p_tmp, p_tmp + (size_t)N_M * HID, HID, HID);

    // ---- GCN layer 2 ----
    {
        GTask ta = { p_tmp,                      W_m2, W_m2, p_A,                     p_A,                     N_M };
        GTask tb = { p_tmp + (size_t)N_M * HID,  W_d2, W_d2, p_A + (size_t)N_M * HID, p_A + (size_t)N_M * HID, N_D };
        k_gemm<<<dim3(1, N_M / 64, 2), 256>>>(ta, tb, HID, 128, HID, nullptr, HID, HID);
    }
    // x0 = relu(gcn2) into xjk cols [0,128)
    k_gcn_agg2<<<wblk(NTOT), GB>>>(p_A, b_m2, b_d2, p_xjk, p_xjk + (size_t)N_M * 224, 224, 224);

    // ---- GATv2 layer 1: xl|xr in ONE dual-W GEMM (K=128, Nc=256+256) ----
    {
        GTask ta = { p_xjk, Wl1, Wr1, p_A, p_B, NTOT };
        k_gemm<<<dim3(4, NTOT / 64, 1), 256>>>(ta, ta, 224, 256, 256, nullptr, 256, 128);
    }
    k_gat_fused<256><<<wblk(NTOT), GB>>>(p_A, p_B, att1, bias1, p_xjk + 128, 224, 1);

    // ---- GATv2 layer 2 (K=64, Nc=128+128) ----
    {
        GTask ta = { p_xjk + 128, Wl2, Wr2, p_A, p_B, NTOT };
        k_gemm<<<dim3(2, NTOT / 64, 1), 256>>>(ta, ta, 224, 128, 128, nullptr, 128, 64);
    }
    k_gat_fused<128><<<wblk(NTOT), GB>>>(p_A, p_B, att2, bias2, p_xjk + 192, 224, 0);

    // ---- JumpingKnowledge linear: out = [x0|x1|x2] @ Wjk + bjk ----
    {
        GTask ta = { p_xjk, Wjk, Wjk, out, out, NTOT };
        k_gemm<<<dim3(1, NTOT / 64, 1), 256>>>(ta, ta, 224, 128, 128, bjk, 128, 224);
    }
}